// round 3
// baseline (speedup 1.0000x reference)
#include <cuda_runtime.h>

#define NN 8192
#define DIN 7
#define DH 8
#define DOUTK 23
#define NCHUNK 32
#define CJ (NN / NCHUNK)      /* 256 j per chunk  */
#define ITILE 256             /* i rows per CTA (128 thr x 2) */
#define NIT (NN / ITILE)      /* 32 i tiles       */

// -------- device scratch (no allocations allowed) --------
__device__ float4 g_wv[NN * 2];            // per j: {wv0..3},{wv4,wv5,wv6,w}
__device__ float g_cA[(NN / 2) * 4];       // per j-pair: {-x0a,-x0b,-x1a,-x1b}
__device__ float g_cB[(NN / 2) * 2];       // per j-pair: {-x2a,-x2b}
__device__ float g_part[NCHUNK][NN][8];    // chunk partial accumulators

__device__ __forceinline__ float leaky(float v) {
    return v >= 0.0f ? v : 0.01f * v;
}

// ---------------- Kernel A: per-node MLP + exp weights ----------------
__global__ void __launch_bounds__(128) prep_kernel(
    const float* __restrict__ x,
    const float* __restrict__ W1, const float* __restrict__ b1,
    const float* __restrict__ W2, const float* __restrict__ b2,
    const float* __restrict__ W3, const float* __restrict__ b3)
{
    __shared__ float sW1[DH * DIN], sb1[DH], sW2[DH * DH], sb2[DH],
                     sW3[DOUTK * DH], sb3[DOUTK];
    __shared__ float sx[128 * DIN];
    const int t = threadIdx.x;
    // coalesced stage of this block's x rows
    {
        const float* xb = x + blockIdx.x * 128 * DIN;
        for (int k = t; k < 128 * DIN; k += 128) sx[k] = xb[k];
    }
    if (t < DH * DIN) sW1[t] = W1[t];
    if (t < DH) { sb1[t] = b1[t]; sb2[t] = b2[t]; }
    if (t < DH * DH) sW2[t] = W2[t];
    for (int k = t; k < DOUTK * DH; k += 128) sW3[k] = W3[k];
    if (t < DOUTK) sb3[t] = b3[t];
    __syncthreads();

    const int j = blockIdx.x * 128 + t;

    float xv[DIN];
#pragma unroll
    for (int k = 0; k < DIN; k++) xv[k] = sx[t * DIN + k];

    float h1[DH];
#pragma unroll
    for (int c = 0; c < DH; c++) {
        float z = sb1[c];
#pragma unroll
        for (int k = 0; k < DIN; k++) z += sW1[c * DIN + k] * xv[k];
        h1[c] = leaky(z);
    }
    float h2[DH];
#pragma unroll
    for (int c = 0; c < DH; c++) {
        float z = sb2[c];
#pragma unroll
        for (int k = 0; k < DH; k++) z += sW2[c * DH + k] * h1[k];
        h2[c] = leaky(z);
    }
    float h3[DOUTK];
#pragma unroll
    for (int c = 0; c < DOUTK; c++) {
        float z = sb3[c];
#pragma unroll
        for (int k = 0; k < DH; k++) z += sW3[c * DH + k] * h2[k];
        h3[c] = z;   // layer 3 is linear
    }

    float s = 0.0f;
#pragma unroll
    for (int k = 0; k < 8; k++) s += h3[DIN + k] * h3[DIN + 8 + k];
    const float w = expf(s);

    g_wv[2 * j]     = make_float4(w * h3[0], w * h3[1], w * h3[2], w * h3[3]);
    g_wv[2 * j + 1] = make_float4(w * h3[4], w * h3[5], w * h3[6], w);

    const int jp = j >> 1, hh = j & 1;
    g_cA[jp * 4 + 0 + hh] = -xv[0];
    g_cA[jp * 4 + 2 + hh] = -xv[1];
    g_cB[jp * 2 + hh]     = -xv[2];
}

// ---------------- probe: shifts ncu capture alignment ----------------
__global__ void probe_kernel() {}

// ---------------- Kernel B: pairwise masked accumulation ----------------
// 128 threads/CTA, each thread owns 2 i-rows; CTA covers 256 i x 256 j.
__global__ void __launch_bounds__(128) pair_kernel(const float* __restrict__ x)
{
    __shared__ float4 s_wv[CJ * 2];       // 8 KB
    __shared__ float4 s_cA[CJ / 2];       // 2 KB
    __shared__ float2 s_cB[CJ / 2];       // 1 KB

    const int t = threadIdx.x;
    const int chunk = blockIdx.x;
    const int itile = blockIdx.y;

    {
        const float4* gwv = g_wv + chunk * CJ * 2;
        for (int k = t; k < CJ * 2; k += 128) s_wv[k] = gwv[k];
        const float4* gca = reinterpret_cast<const float4*>(g_cA) + chunk * (CJ / 2);
        if (t < CJ / 2) s_cA[t] = gca[t];
        const float2* gcb = reinterpret_cast<const float2*>(g_cB) + chunk * (CJ / 2);
        if (t < CJ / 2) s_cB[t] = gcb[t];
    }
    __syncthreads();

    const int i0 = itile * ITILE + t;
    const int i1 = i0 + 128;

    unsigned long long cA0, cB0, cC0, cA1, cB1, cC1;
    {
        const float a0 = __ldg(&x[i0 * DIN + 0]);
        const float a1 = __ldg(&x[i0 * DIN + 1]);
        const float a2 = __ldg(&x[i0 * DIN + 2]);
        const float b0 = __ldg(&x[i1 * DIN + 0]);
        const float b1 = __ldg(&x[i1 * DIN + 1]);
        const float b2 = __ldg(&x[i1 * DIN + 2]);
        asm("mov.b64 %0, {%1, %1};" : "=l"(cA0) : "f"(a0));
        asm("mov.b64 %0, {%1, %1};" : "=l"(cB0) : "f"(a1));
        asm("mov.b64 %0, {%1, %1};" : "=l"(cC0) : "f"(a2));
        asm("mov.b64 %0, {%1, %1};" : "=l"(cA1) : "f"(b0));
        asm("mov.b64 %0, {%1, %1};" : "=l"(cB1) : "f"(b1));
        asm("mov.b64 %0, {%1, %1};" : "=l"(cC1) : "f"(b2));
    }

    unsigned long long a00 = 0ull, a01 = 0ull, a02 = 0ull, a03 = 0ull;
    unsigned long long a10 = 0ull, a11 = 0ull, a12 = 0ull, a13 = 0ull;

    const ulonglong2* wvp = reinterpret_cast<const ulonglong2*>(s_wv);
    const ulonglong2* cap = reinterpret_cast<const ulonglong2*>(s_cA);
    const unsigned long long* cbp =
        reinterpret_cast<const unsigned long long*>(s_cB);

#pragma unroll 2
    for (int jp = 0; jp < CJ / 2; jp++) {
        const ulonglong2 ca = cap[jp];
        const unsigned long long cb = cbp[jp];
        const ulonglong2 wA = wvp[4 * jp + 0];
        const ulonglong2 wB = wvp[4 * jp + 1];
        const ulonglong2 wC = wvp[4 * jp + 2];
        const ulonglong2 wD = wvp[4 * jp + 3];
        // d = (|ci0-cj0| + |ci1-cj1|) + |ci2-cj2|  (reference order, j-coords
        // pre-negated). Two j lanes per f32x2; two i rows per thread.
        asm("{\n\t"
            ".reg .b64 u0, u1, u2, d0, d1;\n\t"
            ".reg .b32 ea, eb, ec, ed;\n\t"
            ".reg .pred p0a, p0b, p1a, p1b;\n\t"
            "add.rn.f32x2 u0, %8, %14;\n\t"
            "add.rn.f32x2 u1, %9, %15;\n\t"
            "add.rn.f32x2 u2, %10, %16;\n\t"
            "and.b64 u0, u0, 0x7FFFFFFF7FFFFFFF;\n\t"
            "and.b64 u1, u1, 0x7FFFFFFF7FFFFFFF;\n\t"
            "and.b64 u2, u2, 0x7FFFFFFF7FFFFFFF;\n\t"
            "add.rn.f32x2 d0, u0, u1;\n\t"
            "add.rn.f32x2 d0, d0, u2;\n\t"
            "add.rn.f32x2 u0, %11, %14;\n\t"
            "add.rn.f32x2 u1, %12, %15;\n\t"
            "add.rn.f32x2 u2, %13, %16;\n\t"
            "and.b64 u0, u0, 0x7FFFFFFF7FFFFFFF;\n\t"
            "and.b64 u1, u1, 0x7FFFFFFF7FFFFFFF;\n\t"
            "and.b64 u2, u2, 0x7FFFFFFF7FFFFFFF;\n\t"
            "add.rn.f32x2 d1, u0, u1;\n\t"
            "add.rn.f32x2 d1, d1, u2;\n\t"
            "mov.b64 {ea, eb}, d0;\n\t"
            "mov.b64 {ec, ed}, d1;\n\t"
            "setp.le.u32 p0a, ea, 0x40666666;\n\t"
            "setp.le.u32 p0b, eb, 0x40666666;\n\t"
            "setp.le.u32 p1a, ec, 0x40666666;\n\t"
            "setp.le.u32 p1b, ed, 0x40666666;\n\t"
            "@p0a add.rn.f32x2 %0, %0, %17;\n\t"
            "@p0a add.rn.f32x2 %1, %1, %18;\n\t"
            "@p0a add.rn.f32x2 %2, %2, %19;\n\t"
            "@p0a add.rn.f32x2 %3, %3, %20;\n\t"
            "@p0b add.rn.f32x2 %0, %0, %21;\n\t"
            "@p0b add.rn.f32x2 %1, %1, %22;\n\t"
            "@p0b add.rn.f32x2 %2, %2, %23;\n\t"
            "@p0b add.rn.f32x2 %3, %3, %24;\n\t"
            "@p1a add.rn.f32x2 %4, %4, %17;\n\t"
            "@p1a add.rn.f32x2 %5, %5, %18;\n\t"
            "@p1a add.rn.f32x2 %6, %6, %19;\n\t"
            "@p1a add.rn.f32x2 %7, %7, %20;\n\t"
            "@p1b add.rn.f32x2 %4, %4, %21;\n\t"
            "@p1b add.rn.f32x2 %5, %5, %22;\n\t"
            "@p1b add.rn.f32x2 %6, %6, %23;\n\t"
            "@p1b add.rn.f32x2 %7, %7, %24;\n\t"
            "}"
            : "+l"(a00), "+l"(a01), "+l"(a02), "+l"(a03),
              "+l"(a10), "+l"(a11), "+l"(a12), "+l"(a13)
            : "l"(cA0), "l"(cB0), "l"(cC0),
              "l"(cA1), "l"(cB1), "l"(cC1),
              "l"(ca.x), "l"(ca.y), "l"(cb),
              "l"(wA.x), "l"(wA.y), "l"(wB.x), "l"(wB.y),
              "l"(wC.x), "l"(wC.y), "l"(wD.x), "l"(wD.y));
    }

    ulonglong2* p0 = reinterpret_cast<ulonglong2*>(&g_part[chunk][i0][0]);
    p0[0] = make_ulonglong2(a00, a01);
    p0[1] = make_ulonglong2(a02, a03);
    ulonglong2* p1 = reinterpret_cast<ulonglong2*>(&g_part[chunk][i1][0]);
    p1[0] = make_ulonglong2(a10, a11);
    p1[1] = make_ulonglong2(a12, a13);
}

// ---------------- Kernel C: reduce partials + final MLP ----------------
__global__ void __launch_bounds__(128) final_kernel(
    const float* __restrict__ x,
    const float* __restrict__ We, const float* __restrict__ be,
    const float* __restrict__ Wd, const float* __restrict__ bd,
    float* __restrict__ out)
{
    __shared__ float sWe[DH * 2 * DIN], sbe[DH], sWd[DIN * DH], sbd[DIN];
    const int t = threadIdx.x;
    if (t < DH * 2 * DIN) sWe[t] = We[t];
    if (t < DH) sbe[t] = be[t];
    if (t < DIN * DH) sWd[t] = Wd[t];
    if (t < DIN) sbd[t] = bd[t];
    __syncthreads();

    const int i = blockIdx.x * 128 + t;

    float a[8];
#pragma unroll
    for (int k = 0; k < 8; k++) a[k] = 0.0f;
#pragma unroll
    for (int c = 0; c < NCHUNK; c++) {
        const float4* p = reinterpret_cast<const float4*>(&g_part[c][i][0]);
        const float4 pa = p[0], pb = p[1];
        a[0] += pa.x; a[1] += pa.y; a[2] += pa.z; a[3] += pa.w;
        a[4] += pb.x; a[5] += pb.y; a[6] += pb.z; a[7] += pb.w;
    }
    // subtract self contribution (self-pair always passes d=0 <= cutoff)
    const float4 wa = g_wv[2 * i], wb = g_wv[2 * i + 1];
    a[0] -= wa.x; a[1] -= wa.y; a[2] -= wa.z; a[3] -= wa.w;
    a[4] -= wb.x; a[5] -= wb.y; a[6] -= wb.z;
    const float denom = a[7] - wb.w;
    const float inv = 1.0f / fmaxf(denom, 1e-30f);

    float agg[DIN];
#pragma unroll
    for (int k = 0; k < DIN; k++) agg[k] = a[k] * inv;

    float xv[DIN];
#pragma unroll
    for (int k = 0; k < DIN; k++) xv[k] = x[i * DIN + k];

    float codes[DH];
#pragma unroll
    for (int c = 0; c < DH; c++) {
        float z = sbe[c];
#pragma unroll
        for (int k = 0; k < DIN; k++) z += sWe[c * (2 * DIN) + k] * xv[k];
#pragma unroll
        for (int k = 0; k < DIN; k++) z += sWe[c * (2 * DIN) + DIN + k] * agg[k];
        codes[c] = leaky(z);
    }
#pragma unroll
    for (int d = 0; d < DIN; d++) {
        float z = sbd[d];
#pragma unroll
        for (int c = 0; c < DH; c++) z += sWd[d * DH + c] * codes[c];
        out[i * DIN + d] = z;
    }
}

// ---------------- launch ----------------
extern "C" void kernel_launch(void* const* d_in, const int* in_sizes, int n_in,
                              void* d_out, int out_size)
{
    const float* x  = (const float*)d_in[0];
    const float* W1 = (const float*)d_in[1];
    const float* b1 = (const float*)d_in[2];
    const float* W2 = (const float*)d_in[3];
    const float* b2 = (const float*)d_in[4];
    const float* W3 = (const float*)d_in[5];
    const float* b3 = (const float*)d_in[6];
    const float* We = (const float*)d_in[7];
    const float* be = (const float*)d_in[8];
    const float* Wd = (const float*)d_in[9];
    const float* bd = (const float*)d_in[10];
    float* out = (float*)d_out;

    prep_kernel<<<NN / 128, 128>>>(x, W1, b1, W2, b2, W3, b3);
    probe_kernel<<<1, 32>>>();
    dim3 grid(NCHUNK, NIT);
    pair_kernel<<<grid, 128>>>(x);
    final_kernel<<<NN / 128, 128>>>(x, We, be, Wd, bd, out);
}

// round 6
// speedup vs baseline: 1.0339x; 1.0339x over previous
#include <cuda_runtime.h>

#define NN 8192
#define DIN 7
#define DH 8
#define DOUTK 23
#define NCHUNK 32
#define CJ (NN / NCHUNK)      /* 256 j per chunk  */
#define ITILE 256             /* i rows per CTA (128 thr x 2) */
#define NIT (NN / ITILE)      /* 32 i tiles       */

// -------- device scratch (no allocations allowed) --------
__device__ float4 g_wv[NN * 2];            // per j: {wv0..3},{wv4,wv5,wv6,w}
__device__ float g_cA[(NN / 2) * 4];       // per j-pair: {-x0a,-x0b,-x1a,-x1b}
__device__ float g_cB[(NN / 2) * 2];       // per j-pair: {-x2a,-x2b}
__device__ float g_part[NCHUNK][NN][8];    // chunk partial accumulators
__device__ float g_agg[NN * 8];            // reduced accumulators

__device__ __forceinline__ float leaky(float v) {
    return v >= 0.0f ? v : 0.01f * v;
}

// ---------------- Kernel A: per-node MLP + exp weights ----------------
// 32-thread CTAs x 256 to spread latency-bound MLP across all SMs.
__global__ void __launch_bounds__(32) prep_kernel(
    const float* __restrict__ x,
    const float* __restrict__ W1, const float* __restrict__ b1,
    const float* __restrict__ W2, const float* __restrict__ b2,
    const float* __restrict__ W3, const float* __restrict__ b3)
{
    __shared__ float sW1[DH * DIN], sb1[DH], sW2[DH * DH], sb2[DH],
                     sW3[DOUTK * DH], sb3[DOUTK];
    __shared__ float sx[32 * DIN];
    const int t = threadIdx.x;
    {
        const float* xb = x + blockIdx.x * 32 * DIN;
        for (int k = t; k < 32 * DIN; k += 32) sx[k] = xb[k];
        for (int k = t; k < DH * DIN; k += 32) sW1[k] = W1[k];
        for (int k = t; k < DH * DH; k += 32) sW2[k] = W2[k];
        for (int k = t; k < DOUTK * DH; k += 32) sW3[k] = W3[k];
        if (t < DH) { sb1[t] = b1[t]; sb2[t] = b2[t]; }
        if (t < DOUTK) sb3[t] = b3[t];
    }
    __syncthreads();

    const int j = blockIdx.x * 32 + t;

    float xv[DIN];
#pragma unroll
    for (int k = 0; k < DIN; k++) xv[k] = sx[t * DIN + k];

    float h1[DH];
#pragma unroll
    for (int c = 0; c < DH; c++) {
        float z = sb1[c];
#pragma unroll
        for (int k = 0; k < DIN; k++) z += sW1[c * DIN + k] * xv[k];
        h1[c] = leaky(z);
    }
    float h2[DH];
#pragma unroll
    for (int c = 0; c < DH; c++) {
        float z = sb2[c];
#pragma unroll
        for (int k = 0; k < DH; k++) z += sW2[c * DH + k] * h1[k];
        h2[c] = leaky(z);
    }
    float h3[DOUTK];
#pragma unroll
    for (int c = 0; c < DOUTK; c++) {
        float z = sb3[c];
#pragma unroll
        for (int k = 0; k < DH; k++) z += sW3[c * DH + k] * h2[k];
        h3[c] = z;   // layer 3 is linear
    }

    float s = 0.0f;
#pragma unroll
    for (int k = 0; k < 8; k++) s += h3[DIN + k] * h3[DIN + 8 + k];
    const float w = expf(s);

    g_wv[2 * j]     = make_float4(w * h3[0], w * h3[1], w * h3[2], w * h3[3]);
    g_wv[2 * j + 1] = make_float4(w * h3[4], w * h3[5], w * h3[6], w);

    const int jp = j >> 1, hh = j & 1;
    g_cA[jp * 4 + 0 + hh] = -xv[0];
    g_cA[jp * 4 + 2 + hh] = -xv[1];
    g_cB[jp * 2 + hh]     = -xv[2];
}

// ---------------- Kernel B: pairwise masked accumulation ----------------
// 128 threads/CTA, each thread owns 2 i-rows; CTA covers 256 i x 256 j.
__global__ void __launch_bounds__(128) pair_kernel(const float* __restrict__ x)
{
    __shared__ float4 s_wv[CJ * 2];       // 8 KB
    __shared__ float4 s_cA[CJ / 2];       // 2 KB
    __shared__ float2 s_cB[CJ / 2];       // 1 KB

    const int t = threadIdx.x;
    const int chunk = blockIdx.x;
    const int itile = blockIdx.y;

    {
        const float4* gwv = g_wv + chunk * CJ * 2;
        for (int k = t; k < CJ * 2; k += 128) s_wv[k] = gwv[k];
        const float4* gca = reinterpret_cast<const float4*>(g_cA) + chunk * (CJ / 2);
        if (t < CJ / 2) s_cA[t] = gca[t];
        const float2* gcb = reinterpret_cast<const float2*>(g_cB) + chunk * (CJ / 2);
        if (t < CJ / 2) s_cB[t] = gcb[t];
    }
    __syncthreads();

    const int i0 = itile * ITILE + t;
    const int i1 = i0 + 128;

    unsigned long long cA0, cB0, cC0, cA1, cB1, cC1;
    {
        const float a0 = __ldg(&x[i0 * DIN + 0]);
        const float a1 = __ldg(&x[i0 * DIN + 1]);
        const float a2 = __ldg(&x[i0 * DIN + 2]);
        const float b0 = __ldg(&x[i1 * DIN + 0]);
        const float b1 = __ldg(&x[i1 * DIN + 1]);
        const float b2 = __ldg(&x[i1 * DIN + 2]);
        asm("mov.b64 %0, {%1, %1};" : "=l"(cA0) : "f"(a0));
        asm("mov.b64 %0, {%1, %1};" : "=l"(cB0) : "f"(a1));
        asm("mov.b64 %0, {%1, %1};" : "=l"(cC0) : "f"(a2));
        asm("mov.b64 %0, {%1, %1};" : "=l"(cA1) : "f"(b0));
        asm("mov.b64 %0, {%1, %1};" : "=l"(cB1) : "f"(b1));
        asm("mov.b64 %0, {%1, %1};" : "=l"(cC1) : "f"(b2));
    }

    unsigned long long a00 = 0ull, a01 = 0ull, a02 = 0ull, a03 = 0ull;
    unsigned long long a10 = 0ull, a11 = 0ull, a12 = 0ull, a13 = 0ull;

    const ulonglong2* wvp = reinterpret_cast<const ulonglong2*>(s_wv);
    const ulonglong2* cap = reinterpret_cast<const ulonglong2*>(s_cA);
    const unsigned long long* cbp =
        reinterpret_cast<const unsigned long long*>(s_cB);

#pragma unroll 2
    for (int jp = 0; jp < CJ / 2; jp++) {
        const ulonglong2 ca = cap[jp];
        const unsigned long long cb = cbp[jp];
        const ulonglong2 wA = wvp[4 * jp + 0];
        const ulonglong2 wB = wvp[4 * jp + 1];
        const ulonglong2 wC = wvp[4 * jp + 2];
        const ulonglong2 wD = wvp[4 * jp + 3];
        // d = (|ci0-cj0| + |ci1-cj1|) + |ci2-cj2|  (reference order, j-coords
        // pre-negated). Two j lanes per f32x2; two i rows per thread.
        asm("{\n\t"
            ".reg .b64 u0, u1, u2, d0, d1;\n\t"
            ".reg .b32 ea, eb, ec, ed;\n\t"
            ".reg .pred p0a, p0b, p1a, p1b;\n\t"
            "add.rn.f32x2 u0, %8, %14;\n\t"
            "add.rn.f32x2 u1, %9, %15;\n\t"
            "add.rn.f32x2 u2, %10, %16;\n\t"
            "and.b64 u0, u0, 0x7FFFFFFF7FFFFFFF;\n\t"
            "and.b64 u1, u1, 0x7FFFFFFF7FFFFFFF;\n\t"
            "and.b64 u2, u2, 0x7FFFFFFF7FFFFFFF;\n\t"
            "add.rn.f32x2 d0, u0, u1;\n\t"
            "add.rn.f32x2 d0, d0, u2;\n\t"
            "add.rn.f32x2 u0, %11, %14;\n\t"
            "add.rn.f32x2 u1, %12, %15;\n\t"
            "add.rn.f32x2 u2, %13, %16;\n\t"
            "and.b64 u0, u0, 0x7FFFFFFF7FFFFFFF;\n\t"
            "and.b64 u1, u1, 0x7FFFFFFF7FFFFFFF;\n\t"
            "and.b64 u2, u2, 0x7FFFFFFF7FFFFFFF;\n\t"
            "add.rn.f32x2 d1, u0, u1;\n\t"
            "add.rn.f32x2 d1, d1, u2;\n\t"
            "mov.b64 {ea, eb}, d0;\n\t"
            "mov.b64 {ec, ed}, d1;\n\t"
            "setp.le.u32 p0a, ea, 0x40666666;\n\t"
            "setp.le.u32 p0b, eb, 0x40666666;\n\t"
            "setp.le.u32 p1a, ec, 0x40666666;\n\t"
            "setp.le.u32 p1b, ed, 0x40666666;\n\t"
            "@p0a add.rn.f32x2 %0, %0, %17;\n\t"
            "@p0a add.rn.f32x2 %1, %1, %18;\n\t"
            "@p0a add.rn.f32x2 %2, %2, %19;\n\t"
            "@p0a add.rn.f32x2 %3, %3, %20;\n\t"
            "@p0b add.rn.f32x2 %0, %0, %21;\n\t"
            "@p0b add.rn.f32x2 %1, %1, %22;\n\t"
            "@p0b add.rn.f32x2 %2, %2, %23;\n\t"
            "@p0b add.rn.f32x2 %3, %3, %24;\n\t"
            "@p1a add.rn.f32x2 %4, %4, %17;\n\t"
            "@p1a add.rn.f32x2 %5, %5, %18;\n\t"
            "@p1a add.rn.f32x2 %6, %6, %19;\n\t"
            "@p1a add.rn.f32x2 %7, %7, %20;\n\t"
            "@p1b add.rn.f32x2 %4, %4, %21;\n\t"
            "@p1b add.rn.f32x2 %5, %5, %22;\n\t"
            "@p1b add.rn.f32x2 %6, %6, %23;\n\t"
            "@p1b add.rn.f32x2 %7, %7, %24;\n\t"
            "}"
            : "+l"(a00), "+l"(a01), "+l"(a02), "+l"(a03),
              "+l"(a10), "+l"(a11), "+l"(a12), "+l"(a13)
            : "l"(cA0), "l"(cB0), "l"(cC0),
              "l"(cA1), "l"(cB1), "l"(cC1),
              "l"(ca.x), "l"(ca.y), "l"(cb),
              "l"(wA.x), "l"(wA.y), "l"(wB.x), "l"(wB.y),
              "l"(wC.x), "l"(wC.y), "l"(wD.x), "l"(wD.y));
    }

    ulonglong2* p0 = reinterpret_cast<ulonglong2*>(&g_part[chunk][i0][0]);
    p0[0] = make_ulonglong2(a00, a01);
    p0[1] = make_ulonglong2(a02, a03);
    ulonglong2* p1 = reinterpret_cast<ulonglong2*>(&g_part[chunk][i1][0]);
    p1[0] = make_ulonglong2(a10, a11);
    p1[1] = make_ulonglong2(a12, a13);
}

// ---------------- Kernel C: coalesced chunk reduction ----------------
// One thread per (i, channel): consecutive threads read consecutive floats
// within each chunk plane -> fully-coalesced 8 MB stream across the chip.
__global__ void __launch_bounds__(256) reduce_kernel()
{
    const int tid = blockIdx.x * 256 + threadIdx.x;   // i*8 + ch
    const float* base = &g_part[0][0][0];
    float s = 0.0f;
#pragma unroll
    for (int c = 0; c < NCHUNK; c++)                  // ascending: keeps
        s += base[c * (NN * 8) + tid];                // prior sum order
    g_agg[tid] = s;
}

// ---------------- Kernel D: final MLP ----------------
// 32-thread CTAs x 256 to spread latency-bound MLP across all SMs.
__global__ void __launch_bounds__(32) final_kernel(
    const float* __restrict__ x,
    const float* __restrict__ We, const float* __restrict__ be,
    const float* __restrict__ Wd, const float* __restrict__ bd,
    float* __restrict__ out)
{
    __shared__ float sWe[DH * 2 * DIN], sbe[DH], sWd[DIN * DH], sbd[DIN];
    const int t = threadIdx.x;
    for (int k = t; k < DH * 2 * DIN; k += 32) sWe[k] = We[k];
    for (int k = t; k < DIN * DH; k += 32) sWd[k] = Wd[k];
    if (t < DH) sbe[t] = be[t];
    if (t < DIN) sbd[t] = bd[t];
    __syncthreads();

    const int i = blockIdx.x * 32 + t;

    float a[8];
    {
        const float4* p = reinterpret_cast<const float4*>(&g_agg[i * 8]);
        const float4 pa = p[0], pb = p[1];
        a[0] = pa.x; a[1] = pa.y; a[2] = pa.z; a[3] = pa.w;
        a[4] = pb.x; a[5] = pb.y; a[6] = pb.z; a[7] = pb.w;
    }
    // subtract self contribution (self-pair always passes d=0 <= cutoff)
    const float4 wa = g_wv[2 * i], wb = g_wv[2 * i + 1];
    a[0] -= wa.x; a[1] -= wa.y; a[2] -= wa.z; a[3] -= wa.w;
    a[4] -= wb.x; a[5] -= wb.y; a[6] -= wb.z;
    const float denom = a[7] - wb.w;
    const float inv = 1.0f / fmaxf(denom, 1e-30f);

    float agg[DIN];
#pragma unroll
    for (int k = 0; k < DIN; k++) agg[k] = a[k] * inv;

    float xv[DIN];
#pragma unroll
    for (int k = 0; k < DIN; k++) xv[k] = x[i * DIN + k];

    float codes[DH];
#pragma unroll
    for (int c = 0; c < DH; c++) {
        float z = sbe[c];
#pragma unroll
        for (int k = 0; k < DIN; k++) z += sWe[c * (2 * DIN) + k] * xv[k];
#pragma unroll
        for (int k = 0; k < DIN; k++) z += sWe[c * (2 * DIN) + DIN + k] * agg[k];
        codes[c] = leaky(z);
    }
#pragma unroll
    for (int d = 0; d < DIN; d++) {
        float z = sbd[d];
#pragma unroll
        for (int c = 0; c < DH; c++) z += sWd[d * DH + c] * codes[c];
        out[i * DIN + d] = z;
    }
}

// ---------------- launch ----------------
extern "C" void kernel_launch(void* const* d_in, const int* in_sizes, int n_in,
                              void* d_out, int out_size)
{
    const float* x  = (const float*)d_in[0];
    const float* W1 = (const float*)d_in[1];
    const float* b1 = (const float*)d_in[2];
    const float* W2 = (const float*)d_in[3];
    const float* b2 = (const float*)d_in[4];
    const float* W3 = (const float*)d_in[5];
    const float* b3 = (const float*)d_in[6];
    const float* We = (const float*)d_in[7];
    const float* be = (const float*)d_in[8];
    const float* Wd = (const float*)d_in[9];
    const float* bd = (const float*)d_in[10];
    float* out = (float*)d_out;

    prep_kernel<<<NN / 32, 32>>>(x, W1, b1, W2, b2, W3, b3);
    dim3 grid(NCHUNK, NIT);
    pair_kernel<<<grid, 128>>>(x);
    reduce_kernel<<<(NN * 8) / 256, 256>>>();
    final_kernel<<<NN / 32, 32>>>(x, We, be, Wd, bd, out);
}